// round 14
// baseline (speedup 1.0000x reference)
#include <cuda_runtime.h>
#include <cuda_fp16.h>
#include <cstdint>

// Problem constants: B=2, S=2048, D=1024, H=16, hd=64, FF=4096
#define BB 2
#define SS 2048
#define DD 1024
#define HH 16
#define HD 64
#define FF_DIM 4096
#define MTOK (BB*SS)          // 4096 rows

// ---------------------------------------------------------------------------
// Scratch (device globals; no allocation allowed)
// ---------------------------------------------------------------------------
__device__ __half g_qkvf[(size_t)MTOK * 3 * DD];
__device__ __half g_af[(size_t)MTOK * DD];
__device__ float  g_h1pre[(size_t)MTOK * DD];
__device__ float  g_h1[(size_t)MTOK * DD];
__device__ float  g_h2pre[(size_t)MTOK * DD];
__device__ __half g_h1f[(size_t)MTOK * DD];
__device__ __half g_midf[(size_t)MTOK * FF_DIM];
__device__ __half g_xf[(size_t)MTOK * DD];
__device__ __half g_wqf[(size_t)3 * DD * DD];
__device__ __half g_owf[(size_t)DD * DD];
__device__ __half g_w1f[(size_t)FF_DIM * DD];
__device__ __half g_w2f[(size_t)DD * FF_DIM];

// ---------------------------------------------------------------------------
// MMA / ldmatrix / cp.async helpers
// ---------------------------------------------------------------------------
__device__ __forceinline__ uint32_t smem_u32(const void* p) {
    uint32_t a;
    asm("{ .reg .u64 t; cvta.to.shared.u64 t, %1; cvt.u32.u64 %0, t; }"
        : "=r"(a) : "l"(p));
    return a;
}
__device__ __forceinline__ void ldsm4(uint32_t* r, uint32_t a) {
    asm volatile("ldmatrix.sync.aligned.m8n8.x4.shared.b16 {%0,%1,%2,%3}, [%4];"
                 : "=r"(r[0]), "=r"(r[1]), "=r"(r[2]), "=r"(r[3]) : "r"(a));
}
__device__ __forceinline__ void ldsm4t(uint32_t* r, uint32_t a) {
    asm volatile("ldmatrix.sync.aligned.m8n8.x4.trans.shared.b16 {%0,%1,%2,%3}, [%4];"
                 : "=r"(r[0]), "=r"(r[1]), "=r"(r[2]), "=r"(r[3]) : "r"(a));
}
__device__ __forceinline__ void mma16816h(float* c, const uint32_t* a, const uint32_t* b) {
    asm volatile(
        "mma.sync.aligned.m16n8k16.row.col.f32.f16.f16.f32 "
        "{%0,%1,%2,%3}, {%4,%5,%6,%7}, {%8,%9}, {%0,%1,%2,%3};"
        : "+f"(c[0]), "+f"(c[1]), "+f"(c[2]), "+f"(c[3])
        : "r"(a[0]), "r"(a[1]), "r"(a[2]), "r"(a[3]), "r"(b[0]), "r"(b[1]));
}
#define CP16(dst, src) \
    asm volatile("cp.async.cg.shared.global [%0], [%1], 16;" :: "r"(dst), "l"(src) : "memory")
#define CP_COMMIT() asm volatile("cp.async.commit_group;" ::: "memory")
#define CP_WAIT1()  asm volatile("cp.async.wait_group 1;" ::: "memory")
#define CP_WAIT0()  asm volatile("cp.async.wait_group 0;" ::: "memory")

// 128B-row tile: row stride 128B (8 x 16B chunks), chunk swizzled by row&7.
__device__ __forceinline__ uint32_t tile_addr(uint32_t base, int row, int ch) {
    return base + (uint32_t)row * 128u + (uint32_t)((ch ^ (row & 7)) << 4);
}
__device__ __forceinline__ uint32_t pack_h2(float a, float b) {
    __half2 h = __halves2half2(__float2half(a), __float2half(b));
    return *(uint32_t*)&h;
}
__device__ __forceinline__ uint32_t ex2_h2(float a, float b) {
    uint32_t packed = pack_h2(a, b);
    uint32_t r;
    asm("ex2.approx.f16x2 %0, %1;" : "=r"(r) : "r"(packed));
    return r;
}

// ---------------------------------------------------------------------------
// fp16 1-term GEMM with fragment double-buffering: ldsm for ks+1 overlaps
// MMAs for ks (breaks the ldsm->mma RAW serialization).
// K-stage 64: 3 stages x 32KB = 96KB smem; 2 CTAs/SM.
// ---------------------------------------------------------------------------
#define GEMM1_SMEM (3 * 32768)   // 96KB

__global__ __launch_bounds__(256, 2) void gemm_f16_1t(
    const __half* __restrict__ A, const __half* __restrict__ W,
    const float* __restrict__ bias, const float* __restrict__ res,
    float* __restrict__ C, __half* __restrict__ Cf,
    float* __restrict__ kd, float* __restrict__ vd,
    int M, int N, int K, int relu)
{
    extern __shared__ char dsm[];
    const uint32_t sb = smem_u32(dsm);

    const int tid = threadIdx.x;
    const int lid = tid & 31;
    const int wid = tid >> 5;
    const int wm = wid & 1;
    const int wn = wid >> 1;
    const int bm = blockIdx.y * 128, bn = blockIdx.x * 128;

    const __half* gA = A + (size_t)bm * K;
    const __half* gW = W + (size_t)bn * K;

    float acc[4][4][4];
#pragma unroll
    for (int i = 0; i < 4; ++i)
#pragma unroll
        for (int j = 0; j < 4; ++j)
#pragma unroll
            for (int k = 0; k < 4; ++k) acc[i][j][k] = 0.f;

    const int NC = K >> 6;           // K-chunks of 64

    auto load_stage = [&](int stage, int kk) {
        const uint32_t stb = sb + (uint32_t)stage * 32768u;
        const int r  = tid >> 1;
        const int c0 = (tid & 1) * 4;
        const __half* ga = gA + kk + (size_t)r * K;
        const __half* gw = gW + kk + (size_t)r * K;
#pragma unroll
        for (int j = 0; j < 4; ++j) {
            const int ch = c0 + j;
            CP16(tile_addr(stb, r, ch),            (const char*)(ga + ch * 8));
            CP16(tile_addr(stb + 16384u, r, ch),   (const char*)(gw + ch * 8));
        }
        CP_COMMIT();
    };

    load_stage(0, 0);
    load_stage(1, 64);

    const int arow = lid & 15;
    const int achd = lid >> 4;
    const int ar = wm * 64 + arow;       // A base row for this lane
    const int br0 = wn * 32 + arow;      // B base rows (two 16-row groups)

    uint32_t af[2][4][4], bf[2][4][2];

    auto load_frags = [&](uint32_t stb, int ks, int buf) {
        const int chk = ks * 2 + achd;
#pragma unroll
        for (int mt = 0; mt < 4; ++mt)
            ldsm4(af[buf][mt], tile_addr(stb, ar + mt * 16, chk));
#pragma unroll
        for (int ntp = 0; ntp < 2; ++ntp) {
            uint32_t t[4];
            ldsm4(t, tile_addr(stb + 16384u, br0 + ntp * 16, chk));
            bf[buf][2 * ntp][0] = t[0]; bf[buf][2 * ntp][1] = t[2];
            bf[buf][2 * ntp + 1][0] = t[1]; bf[buf][2 * ntp + 1][1] = t[3];
        }
    };

    for (int c = 0; c < NC; ++c) {
        if (c < NC - 1) CP_WAIT1(); else CP_WAIT0();
        __syncthreads();
        if (c + 2 < NC) load_stage((c + 2) % 3, (c + 2) << 6);

        const uint32_t stb = sb + (uint32_t)(c % 3) * 32768u;

        load_frags(stb, 0, 0);
#pragma unroll
        for (int ks = 0; ks < 4; ++ks) {
            const int cur = ks & 1;
            if (ks < 3) load_frags(stb, ks + 1, cur ^ 1);
#pragma unroll
            for (int mt = 0; mt < 4; ++mt)
#pragma unroll
                for (int nt = 0; nt < 4; ++nt)
                    mma16816h(acc[mt][nt], af[cur][mt], bf[cur][nt]);
        }
    }

    const int l4 = lid >> 2;
    const int l2 = (lid & 3) * 2;
#pragma unroll
    for (int mt = 0; mt < 4; ++mt) {
#pragma unroll
        for (int nt = 0; nt < 4; ++nt) {
            const int col = bn + wn * 32 + nt * 8 + l2;
#pragma unroll
            for (int half = 0; half < 2; ++half) {
                const int row = bm + wm * 64 + mt * 16 + l4 + half * 8;
                float v0 = acc[mt][nt][2 * half + 0];
                float v1 = acc[mt][nt][2 * half + 1];
                v0 += bias[col]; v1 += bias[col + 1];
                const size_t o = (size_t)row * N + col;
                if (res) { v0 += res[o]; v1 += res[o + 1]; }
                if (relu) { v0 = fmaxf(v0, 0.f); v1 = fmaxf(v1, 0.f); }
                if (C) *(float2*)(C + o) = make_float2(v0, v1);
                if (kd) {
                    if (col >= 2048)
                        *(float2*)(vd + (size_t)row * DD + col - 2048) = make_float2(v0, v1);
                    else if (col >= 1024)
                        *(float2*)(kd + (size_t)row * DD + col - 1024) = make_float2(v0, v1);
                }
                if (Cf) *(uint32_t*)(Cf + o) = pack_h2(v0, v1);
            }
        }
    }
}

// ---------------------------------------------------------------------------
// Fused fp32->fp16 conversion of all 5 arrays in ONE launch.
// ---------------------------------------------------------------------------
#define CVT_TOTAL4 4194304
#define CVT_BLOCKS ((CVT_TOTAL4 / 4) / 256)

__global__ __launch_bounds__(256) void cvt_all_k(
    const float4* __restrict__ s0, const float4* __restrict__ s1,
    const float4* __restrict__ s2, const float4* __restrict__ s3,
    const float4* __restrict__ s4,
    uint32_t* __restrict__ d0, uint32_t* __restrict__ d1,
    uint32_t* __restrict__ d2, uint32_t* __restrict__ d3,
    uint32_t* __restrict__ d4)
{
    const size_t g = (size_t)(blockIdx.x * blockDim.x + threadIdx.x) * 4;
    const float4* s;
    uint32_t* d;
    size_t off;
    if (g < 786432u)       { s = s0; d = d0; off = 0; }
    else if (g < 1048576u) { s = s1; d = d1; off = 786432u; }
    else if (g < 2097152u) { s = s2; d = d2; off = 1048576u; }
    else if (g < 3145728u) { s = s3; d = d3; off = 2097152u; }
    else                   { s = s4; d = d4; off = 3145728u; }
    const size_t i = g - off;
    float4 v0 = s[i], v1 = s[i + 1], v2 = s[i + 2], v3 = s[i + 3];
    d[2 * i + 0] = pack_h2(v0.x, v0.y);
    d[2 * i + 1] = pack_h2(v0.z, v0.w);
    d[2 * i + 2] = pack_h2(v1.x, v1.y);
    d[2 * i + 3] = pack_h2(v1.z, v1.w);
    d[2 * i + 4] = pack_h2(v2.x, v2.y);
    d[2 * i + 5] = pack_h2(v2.z, v2.w);
    d[2 * i + 6] = pack_h2(v3.x, v3.y);
    d[2 * i + 7] = pack_h2(v3.z, v3.w);
}

// ---------------------------------------------------------------------------
// fp16 1-term flash attention, causal, log2-domain softmax via ex2.f16x2.
// Smem: Q 16KB + 3 x (K 8KB + V 8KB) = 64KB. 2 CTAs/SM.
// ---------------------------------------------------------------------------
#define FA_SMEM (16384 + 3 * 16384)   // 64KB

__global__ __launch_bounds__(256, 2) void flash_f16_k(
    const __half* __restrict__ qkv, __half* __restrict__ out)
{
    extern __shared__ char dsm[];
    const uint32_t sb = smem_u32(dsm);
    const uint32_t Qt = sb;

    const int tid = threadIdx.x;
    const int lid = tid & 31;
    const int w   = tid >> 5;
    const int q0  = (gridDim.x - 1 - blockIdx.x) * 128;
    const int b   = blockIdx.y >> 4;
    const int h   = blockIdx.y & 15;
    const size_t grow = (size_t)(b * SS);

    auto load_q = [&]() {
        const int row = tid >> 1;
        const int cb  = (tid & 1) * 4;
        const size_t src = (grow + q0 + row) * 3072 + h * HD;
#pragma unroll
        for (int j = 0; j < 4; ++j) {
            const int ch = cb + j;
            CP16(tile_addr(Qt, row, ch), (const char*)(qkv + src + ch * 8));
        }
    };
    auto load_kv = [&](int buf, int k0) {
        const uint32_t bbase = sb + 16384u + (uint32_t)buf * 16384u;
        const int row = tid >> 2;
        const int cb  = (tid & 3) * 2;
        const size_t srcK = (grow + k0 + row) * 3072 + 1024 + h * HD;
        const size_t srcV = srcK + 1024;
#pragma unroll
        for (int j = 0; j < 2; ++j) {
            const int ch = cb + j;
            const uint32_t off = tile_addr(0, row, ch);
            CP16(bbase + off,          (const char*)(qkv + srcK + ch * 8));
            CP16(bbase + 8192u + off,  (const char*)(qkv + srcV + ch * 8));
        }
    };

    const int nblk = q0 / 64 + 2;

    load_q();
    load_kv(0, 0);
    CP_COMMIT();
    load_kv(1, 64);
    CP_COMMIT();

    const int arow = lid & 15;
    const int achd = lid >> 4;

    uint32_t qf[4][4];
    float of[8][4];
#pragma unroll
    for (int i = 0; i < 8; ++i)
#pragma unroll
        for (int j = 0; j < 4; ++j) of[i][j] = 0.f;
    float m0 = -1e30f, m1 = -1e30f, l0 = 0.f, l1 = 0.f;

    const int row_lo = lid >> 2;
    const float SC = 0.125f * 1.44269504f;   // hd^-0.5 * log2(e)

    for (int c = 0; c < nblk; ++c) {
        if (c < nblk - 1) CP_WAIT1(); else CP_WAIT0();
        __syncthreads();
        if (c + 2 < nblk) { load_kv((c + 2) % 3, (c + 2) * 64); CP_COMMIT(); }

        if (c == 0) {
#pragma unroll
            for (int ks = 0; ks < 4; ++ks)
                ldsm4(qf[ks], tile_addr(Qt, w * 16 + arow, ks * 2 + achd));
        }

        const int k0 = c * 64;
        if (k0 > q0 + w * 16 + 15) continue;

        const uint32_t kb = sb + 16384u + (uint32_t)(c % 3) * 16384u;

        float sf[8][4];
#pragma unroll
        for (int i = 0; i < 8; ++i)
#pragma unroll
            for (int j = 0; j < 4; ++j) sf[i][j] = 0.f;

#pragma unroll
        for (int ks = 0; ks < 4; ++ks) {
            uint32_t bh[8][2];
#pragma unroll
            for (int ntp = 0; ntp < 4; ++ntp) {
                uint32_t t[4];
                ldsm4(t, tile_addr(kb, ntp * 16 + arow, ks * 2 + achd));
                bh[2 * ntp][0] = t[0]; bh[2 * ntp][1] = t[2];
                bh[2 * ntp + 1][0] = t[1]; bh[2 * ntp + 1][1] = t[3];
            }
#pragma unroll
            for (int nt = 0; nt < 8; ++nt) mma16816h(sf[nt], qf[ks], bh[nt]);
        }

        const int grow0 = q0 + w * 16 + row_lo;
        const int grow1 = grow0 + 8;
        const bool need_mask = (k0 + 63 > q0 + w * 16);
#pragma unroll
        for (int nt = 0; nt < 8; ++nt) {
            const int col = k0 + nt * 8 + 2 * (lid & 3);
#pragma unroll
            for (int j = 0; j < 4; ++j) sf[nt][j] *= SC;
            if (need_mask) {
                if (col     > grow0) sf[nt][0] = -1e30f;
                if (col + 1 > grow0) sf[nt][1] = -1e30f;
                if (col     > grow1) sf[nt][2] = -1e30f;
                if (col + 1 > grow1) sf[nt][3] = -1e30f;
            }
        }

        float tm0 = -1e30f, tm1 = -1e30f;
#pragma unroll
        for (int nt = 0; nt < 8; ++nt) {
            tm0 = fmaxf(tm0, fmaxf(sf[nt][0], sf[nt][1]));
            tm1 = fmaxf(tm1, fmaxf(sf[nt][2], sf[nt][3]));
        }
        tm0 = fmaxf(tm0, __shfl_xor_sync(0xffffffffu, tm0, 1));
        tm0 = fmaxf(tm0, __shfl_xor_sync(0xffffffffu, tm0, 2));
        tm1 = fmaxf(tm1, __shfl_xor_sync(0xffffffffu, tm1, 1));
        tm1 = fmaxf(tm1, __shfl_xor_sync(0xffffffffu, tm1, 2));

        const float mn0 = fmaxf(m0, tm0), mn1 = fmaxf(m1, tm1);
        const float cr0 = exp2f(m0 - mn0), cr1 = exp2f(m1 - mn1);
        m0 = mn0; m1 = mn1;

        uint32_t pa[4][4];
        float ps0 = 0.f, ps1 = 0.f;
#pragma unroll
        for (int nt = 0; nt < 8; ++nt) {
            const uint32_t p01 = ex2_h2(sf[nt][0] - mn0, sf[nt][1] - mn0);
            const uint32_t p23 = ex2_h2(sf[nt][2] - mn1, sf[nt][3] - mn1);
            pa[nt >> 1][(nt & 1) * 2 + 0] = p01;
            pa[nt >> 1][(nt & 1) * 2 + 1] = p23;
            const float2 f01 = __half22float2(*(const __half2*)&p01);
            const float2 f23 = __half22float2(*(const __half2*)&p23);
            ps0 += f01.x + f01.y;
            ps1 += f23.x + f23.y;
        }
        ps0 += __shfl_xor_sync(0xffffffffu, ps0, 1);
        ps0 += __shfl_xor_sync(0xffffffffu, ps0, 2);
        ps1 += __shfl_xor_sync(0xffffffffu, ps1, 1);
        ps1 += __shfl_xor_sync(0xffffffffu, ps1, 2);
        l0 = l0 * cr0 + ps0;
        l1 = l1 * cr1 + ps1;
#pragma unroll
        for (int nt = 0; nt < 8; ++nt) {
            of[nt][0] *= cr0; of[nt][1] *= cr0;
            of[nt][2] *= cr1; of[nt][3] *= cr1;
        }

        const uint32_t vb = kb + 8192u;
#pragma unroll
        for (int ks = 0; ks < 4; ++ks) {
            uint32_t vh[8][2];
#pragma unroll
            for (int ntp = 0; ntp < 4; ++ntp) {
                const int krow = ks * 16 + arow;
                uint32_t t[4];
                ldsm4t(t, tile_addr(vb, krow, ntp * 2 + achd));
                vh[2 * ntp][0] = t[0]; vh[2 * ntp][1] = t[1];
                vh[2 * ntp + 1][0] = t[2]; vh[2 * ntp + 1][1] = t[3];
            }
#pragma unroll
            for (int nt = 0; nt < 8; ++nt) mma16816h(of[nt], pa[ks], vh[nt]);
        }
    }

    const float iv0 = 1.0f / l0, iv1 = 1.0f / l1;
    const size_t r0 = (grow + q0 + w * 16 + row_lo) * DD + h * HD;
    const size_t r1 = r0 + 8 * DD;
#pragma unroll
    for (int nt = 0; nt < 8; ++nt) {
        const int cofs = nt * 8 + 2 * (lid & 3);
        *(uint32_t*)(out + r0 + cofs) = pack_h2(of[nt][0] * iv0, of[nt][1] * iv0);
        *(uint32_t*)(out + r1 + cofs) = pack_h2(of[nt][2] * iv1, of[nt][3] * iv1);
    }
}

// ---------------------------------------------------------------------------
// LayerNorm over D=1024; optional fused fp16 single output
// ---------------------------------------------------------------------------
__global__ __launch_bounds__(256) void layernorm_k(
    const float* __restrict__ in, const float* __restrict__ w,
    const float* __restrict__ b, float* __restrict__ out,
    __half* __restrict__ of16)
{
    __shared__ float red[8];
    __shared__ float bval;
    const int tid = threadIdx.x;
    const size_t base = (size_t)blockIdx.x * DD;

    float4 v = ((const float4*)(in + base))[tid];
    float s = v.x + v.y + v.z + v.w;
#pragma unroll
    for (int off = 16; off; off >>= 1) s += __shfl_xor_sync(0xffffffffu, s, off);
    if ((tid & 31) == 0) red[tid >> 5] = s;
    __syncthreads();
    if (tid == 0) {
        float t = 0.f;
#pragma unroll
        for (int i = 0; i < 8; ++i) t += red[i];
        bval = t * (1.0f / DD);
    }
    __syncthreads();
    const float mu = bval;
    __syncthreads();

    float dx = v.x - mu, dy = v.y - mu, dz = v.z - mu, dw = v.w - mu;
    float q = dx * dx + dy * dy + dz * dz + dw * dw;
#pragma unroll
    for (int off = 16; off; off >>= 1) q += __shfl_xor_sync(0xffffffffu, q, off);
    if ((tid & 31) == 0) red[tid >> 5] = q;
    __syncthreads();
    if (tid == 0) {
        float t = 0.f;
#pragma unroll
        for (int i = 0; i < 8; ++i) t += red[i];
        bval = t * (1.0f / DD);
    }
    __syncthreads();
    const float inv = rsqrtf(bval + 1e-5f);

    float4 w4 = ((const float4*)w)[tid];
    float4 b4 = ((const float4*)b)[tid];
    float4 r = make_float4(dx * inv * w4.x + b4.x,
                           dy * inv * w4.y + b4.y,
                           dz * inv * w4.z + b4.z,
                           dw * inv * w4.w + b4.w);
    ((float4*)(out + base))[tid] = r;
    if (of16) {
        *(uint32_t*)(of16 + base + 4 * tid)     = pack_h2(r.x, r.y);
        *(uint32_t*)(of16 + base + 4 * tid + 2) = pack_h2(r.z, r.w);
    }
}

// ---------------------------------------------------------------------------
// Launch
// ---------------------------------------------------------------------------
extern "C" void kernel_launch(void* const* d_in, const int* in_sizes, int n_in,
                              void* d_out, int out_size)
{
    const float* x     = (const float*)d_in[0];
    const float* qkv_w = (const float*)d_in[1];
    const float* qkv_b = (const float*)d_in[2];
    const float* out_w = (const float*)d_in[3];
    const float* out_b = (const float*)d_in[4];
    const float* w1    = (const float*)d_in[5];
    const float* b1    = (const float*)d_in[6];
    const float* w2    = (const float*)d_in[7];
    const float* b2    = (const float*)d_in[8];
    const float* ln1w  = (const float*)d_in[9];
    const float* ln1b  = (const float*)d_in[10];
    const float* ln2w  = (const float*)d_in[11];
    const float* ln2b  = (const float*)d_in[12];

    float* outp = (float*)d_out;
    float* kdst = outp + (size_t)MTOK * DD;
    float* vdst = outp + (size_t)2 * MTOK * DD;

    float *h1pre, *h1, *h2pre;
    __half *qkvf, *af, *h1f, *midf, *xf, *wqf, *owf, *w1f, *w2f;
    cudaGetSymbolAddress((void**)&qkvf,  g_qkvf);
    cudaGetSymbolAddress((void**)&af,    g_af);
    cudaGetSymbolAddress((void**)&h1pre, g_h1pre);
    cudaGetSymbolAddress((void**)&h1,    g_h1);
    cudaGetSymbolAddress((void**)&h2pre, g_h2pre);
    cudaGetSymbolAddress((void**)&h1f,   g_h1f);
    cudaGetSymbolAddress((void**)&midf,  g_midf);
    cudaGetSymbolAddress((void**)&xf,    g_xf);
    cudaGetSymbolAddress((void**)&wqf,   g_wqf);
    cudaGetSymbolAddress((void**)&owf,   g_owf);
    cudaGetSymbolAddress((void**)&w1f,   g_w1f);
    cudaGetSymbolAddress((void**)&w2f,   g_w2f);

    cudaFuncSetAttribute(gemm_f16_1t,
                         cudaFuncAttributeMaxDynamicSharedMemorySize, GEMM1_SMEM);
    cudaFuncSetAttribute(flash_f16_k,
                         cudaFuncAttributeMaxDynamicSharedMemorySize, FA_SMEM);

    // 0) all fp32->fp16 conversions in ONE launch
    cvt_all_k<<<CVT_BLOCKS, 256>>>(
        (const float4*)qkv_w, (const float4*)out_w, (const float4*)w1,
        (const float4*)w2, (const float4*)x,
        (uint32_t*)wqf, (uint32_t*)owf, (uint32_t*)w1f,
        (uint32_t*)w2f, (uint32_t*)xf);

    // 1) QKV projection -> qkv fp16 single; k/v fp32 to d_out
    gemm_f16_1t<<<dim3(3072 / 128, MTOK / 128), 256, GEMM1_SMEM>>>(
        xf, wqf, qkv_b, nullptr, nullptr, qkvf, kdst, vdst,
        MTOK, 3 * DD, DD, 0);
    // 2) flash attention -> attn fp16 single
    flash_f16_k<<<dim3(SS / 128, BB * HH), 256, FA_SMEM>>>(qkvf, af);
    // 3) out projection + residual x -> h1pre
    gemm_f16_1t<<<dim3(DD / 128, MTOK / 128), 256, GEMM1_SMEM>>>(
        af, owf, out_b, x, h1pre, nullptr, nullptr, nullptr,
        MTOK, DD, DD, 0);
    // 4) LN1 -> h1 fp32 + h1f fp16
    layernorm_k<<<MTOK, 256>>>(h1pre, ln1w, ln1b, h1, h1f);
    // 5) MLP up + ReLU -> midf fp16
    gemm_f16_1t<<<dim3(FF_DIM / 128, MTOK / 128), 256, GEMM1_SMEM>>>(
        h1f, w1f, b1, nullptr, nullptr, midf, nullptr, nullptr,
        MTOK, FF_DIM, DD, 1);
    // 6) MLP down + residual h1 -> h2pre fp32
    gemm_f16_1t<<<dim3(DD / 128, MTOK / 128), 256, GEMM1_SMEM>>>(
        midf, w2f, b2, h1, h2pre, nullptr, nullptr, nullptr,
        MTOK, DD, FF_DIM, 0);
    // 7) LN2 -> out
    layernorm_k<<<MTOK, 256>>>(h2pre, ln2w, ln2b, outp, nullptr);
}

// round 15
// speedup vs baseline: 1.0277x; 1.0277x over previous
#include <cuda_runtime.h>
#include <cuda_fp16.h>
#include <cstdint>

// Problem constants: B=2, S=2048, D=1024, H=16, hd=64, FF=4096
#define BB 2
#define SS 2048
#define DD 1024
#define HH 16
#define HD 64
#define FF_DIM 4096
#define MTOK (BB*SS)          // 4096 rows

// ---------------------------------------------------------------------------
// Scratch (device globals; no allocation allowed)
// ---------------------------------------------------------------------------
__device__ __half g_qkvf[(size_t)MTOK * 3 * DD];
__device__ __half g_af[(size_t)MTOK * DD];
__device__ float  g_part[(size_t)2 * MTOK * DD];   // split-K partials (reused)
__device__ float  g_h1[(size_t)MTOK * DD];
__device__ __half g_h1f[(size_t)MTOK * DD];
__device__ __half g_midf[(size_t)MTOK * FF_DIM];
__device__ __half g_xf[(size_t)MTOK * DD];
__device__ __half g_wqf[(size_t)3 * DD * DD];
__device__ __half g_owf[(size_t)DD * DD];
__device__ __half g_w1f[(size_t)FF_DIM * DD];
__device__ __half g_w2f[(size_t)DD * FF_DIM];

// ---------------------------------------------------------------------------
// MMA / ldmatrix / cp.async helpers
// ---------------------------------------------------------------------------
__device__ __forceinline__ uint32_t smem_u32(const void* p) {
    uint32_t a;
    asm("{ .reg .u64 t; cvta.to.shared.u64 t, %1; cvt.u32.u64 %0, t; }"
        : "=r"(a) : "l"(p));
    return a;
}
__device__ __forceinline__ void ldsm4(uint32_t* r, uint32_t a) {
    asm volatile("ldmatrix.sync.aligned.m8n8.x4.shared.b16 {%0,%1,%2,%3}, [%4];"
                 : "=r"(r[0]), "=r"(r[1]), "=r"(r[2]), "=r"(r[3]) : "r"(a));
}
__device__ __forceinline__ void ldsm4t(uint32_t* r, uint32_t a) {
    asm volatile("ldmatrix.sync.aligned.m8n8.x4.trans.shared.b16 {%0,%1,%2,%3}, [%4];"
                 : "=r"(r[0]), "=r"(r[1]), "=r"(r[2]), "=r"(r[3]) : "r"(a));
}
__device__ __forceinline__ void mma16816h(float* c, const uint32_t* a, const uint32_t* b) {
    asm volatile(
        "mma.sync.aligned.m16n8k16.row.col.f32.f16.f16.f32 "
        "{%0,%1,%2,%3}, {%4,%5,%6,%7}, {%8,%9}, {%0,%1,%2,%3};"
        : "+f"(c[0]), "+f"(c[1]), "+f"(c[2]), "+f"(c[3])
        : "r"(a[0]), "r"(a[1]), "r"(a[2]), "r"(a[3]), "r"(b[0]), "r"(b[1]));
}
#define CP16(dst, src) \
    asm volatile("cp.async.cg.shared.global [%0], [%1], 16;" :: "r"(dst), "l"(src) : "memory")
#define CP_COMMIT() asm volatile("cp.async.commit_group;" ::: "memory")
#define CP_WAIT1()  asm volatile("cp.async.wait_group 1;" ::: "memory")
#define CP_WAIT0()  asm volatile("cp.async.wait_group 0;" ::: "memory")

// 128B-row tile: row stride 128B (8 x 16B chunks), chunk swizzled by row&7.
__device__ __forceinline__ uint32_t tile_addr(uint32_t base, int row, int ch) {
    return base + (uint32_t)row * 128u + (uint32_t)((ch ^ (row & 7)) << 4);
}
__device__ __forceinline__ uint32_t pack_h2(float a, float b) {
    __half2 h = __halves2half2(__float2half(a), __float2half(b));
    return *(uint32_t*)&h;
}
__device__ __forceinline__ uint32_t ex2_h2(float a, float b) {
    uint32_t packed = pack_h2(a, b);
    uint32_t r;
    asm("ex2.approx.f16x2 %0, %1;" : "=r"(r) : "r"(packed));
    return r;
}

// ---------------------------------------------------------------------------
// fp16 1-term GEMM. Supports split-K via blockIdx.z: each z-slice computes
// K/gridDim.z and writes its fp32 partial to C + z*M*N (bias nullable).
// K-stage 64: 3 stages x 32KB = 96KB smem; 2 CTAs/SM.
// ---------------------------------------------------------------------------
#define GEMM1_SMEM (3 * 32768)   // 96KB

__global__ __launch_bounds__(256, 2) void gemm_f16_1t(
    const __half* __restrict__ A, const __half* __restrict__ W,
    const float* __restrict__ bias, const float* __restrict__ res,
    float* __restrict__ C, __half* __restrict__ Cf,
    float* __restrict__ kd, float* __restrict__ vd,
    int M, int N, int K, int relu)
{
    extern __shared__ char dsm[];
    const uint32_t sb = smem_u32(dsm);

    const int tid = threadIdx.x;
    const int lid = tid & 31;
    const int wid = tid >> 5;
    const int wm = wid & 1;
    const int wn = wid >> 1;
    const int bm = blockIdx.y * 128, bn = blockIdx.x * 128;
    const int kz = blockIdx.z;
    const int Ks = K / gridDim.z;

    const __half* gA = A + (size_t)bm * K + (size_t)kz * Ks;
    const __half* gW = W + (size_t)bn * K + (size_t)kz * Ks;
    float* Cz = C ? C + (size_t)kz * M * N : nullptr;

    float acc[4][4][4];
#pragma unroll
    for (int i = 0; i < 4; ++i)
#pragma unroll
        for (int j = 0; j < 4; ++j)
#pragma unroll
            for (int k = 0; k < 4; ++k) acc[i][j][k] = 0.f;

    const int NC = Ks >> 6;           // K-chunks of 64

    auto load_stage = [&](int stage, int kk) {
        const uint32_t stb = sb + (uint32_t)stage * 32768u;
        const int r  = tid >> 1;
        const int c0 = (tid & 1) * 4;
        const __half* ga = gA + kk + (size_t)r * K;
        const __half* gw = gW + kk + (size_t)r * K;
#pragma unroll
        for (int j = 0; j < 4; ++j) {
            const int ch = c0 + j;
            CP16(tile_addr(stb, r, ch),            (const char*)(ga + ch * 8));
            CP16(tile_addr(stb + 16384u, r, ch),   (const char*)(gw + ch * 8));
        }
        CP_COMMIT();
    };

    load_stage(0, 0);
    load_stage(1, 64);

    const int arow = lid & 15;
    const int achd = lid >> 4;

    for (int c = 0; c < NC; ++c) {
        if (c < NC - 1) CP_WAIT1(); else CP_WAIT0();
        __syncthreads();
        if (c + 2 < NC) load_stage((c + 2) % 3, (c + 2) << 6);

        const uint32_t stb = sb + (uint32_t)(c % 3) * 32768u;

#pragma unroll
        for (int ks = 0; ks < 4; ++ks) {
            const int chk = ks * 2 + achd;
            uint32_t af[4][4];
#pragma unroll
            for (int mt = 0; mt < 4; ++mt) {
                const int r = wm * 64 + mt * 16 + arow;
                ldsm4(af[mt], tile_addr(stb, r, chk));
            }
            uint32_t bf[4][2];
#pragma unroll
            for (int ntp = 0; ntp < 2; ++ntp) {
                const int r = wn * 32 + ntp * 16 + arow;
                uint32_t t[4];
                ldsm4(t, tile_addr(stb + 16384u, r, chk));
                bf[2 * ntp][0] = t[0]; bf[2 * ntp][1] = t[2];
                bf[2 * ntp + 1][0] = t[1]; bf[2 * ntp + 1][1] = t[3];
            }
#pragma unroll
            for (int mt = 0; mt < 4; ++mt)
#pragma unroll
                for (int nt = 0; nt < 4; ++nt)
                    mma16816h(acc[mt][nt], af[mt], bf[nt]);
        }
    }

    const int l4 = lid >> 2;
    const int l2 = (lid & 3) * 2;
#pragma unroll
    for (int mt = 0; mt < 4; ++mt) {
#pragma unroll
        for (int nt = 0; nt < 4; ++nt) {
            const int col = bn + wn * 32 + nt * 8 + l2;
#pragma unroll
            for (int half = 0; half < 2; ++half) {
                const int row = bm + wm * 64 + mt * 16 + l4 + half * 8;
                float v0 = acc[mt][nt][2 * half + 0];
                float v1 = acc[mt][nt][2 * half + 1];
                if (bias) { v0 += bias[col]; v1 += bias[col + 1]; }
                const size_t o = (size_t)row * N + col;
                if (res) { v0 += res[o]; v1 += res[o + 1]; }
                if (relu) { v0 = fmaxf(v0, 0.f); v1 = fmaxf(v1, 0.f); }
                if (Cz) *(float2*)(Cz + o) = make_float2(v0, v1);
                if (kd) {
                    if (col >= 2048)
                        *(float2*)(vd + (size_t)row * DD + col - 2048) = make_float2(v0, v1);
                    else if (col >= 1024)
                        *(float2*)(kd + (size_t)row * DD + col - 1024) = make_float2(v0, v1);
                }
                if (Cf) *(uint32_t*)(Cf + o) = pack_h2(v0, v1);
            }
        }
    }
}

// ---------------------------------------------------------------------------
// Fused fp32->fp16 conversion of all 5 arrays in ONE launch.
// ---------------------------------------------------------------------------
#define CVT_TOTAL4 4194304
#define CVT_BLOCKS ((CVT_TOTAL4 / 4) / 256)

__global__ __launch_bounds__(256) void cvt_all_k(
    const float4* __restrict__ s0, const float4* __restrict__ s1,
    const float4* __restrict__ s2, const float4* __restrict__ s3,
    const float4* __restrict__ s4,
    uint32_t* __restrict__ d0, uint32_t* __restrict__ d1,
    uint32_t* __restrict__ d2, uint32_t* __restrict__ d3,
    uint32_t* __restrict__ d4)
{
    const size_t g = (size_t)(blockIdx.x * blockDim.x + threadIdx.x) * 4;
    const float4* s;
    uint32_t* d;
    size_t off;
    if (g < 786432u)       { s = s0; d = d0; off = 0; }
    else if (g < 1048576u) { s = s1; d = d1; off = 786432u; }
    else if (g < 2097152u) { s = s2; d = d2; off = 1048576u; }
    else if (g < 3145728u) { s = s3; d = d3; off = 2097152u; }
    else                   { s = s4; d = d4; off = 3145728u; }
    const size_t i = g - off;
    float4 v0 = s[i], v1 = s[i + 1], v2 = s[i + 2], v3 = s[i + 3];
    d[2 * i + 0] = pack_h2(v0.x, v0.y);
    d[2 * i + 1] = pack_h2(v0.z, v0.w);
    d[2 * i + 2] = pack_h2(v1.x, v1.y);
    d[2 * i + 3] = pack_h2(v1.z, v1.w);
    d[2 * i + 4] = pack_h2(v2.x, v2.y);
    d[2 * i + 5] = pack_h2(v2.z, v2.w);
    d[2 * i + 6] = pack_h2(v3.x, v3.y);
    d[2 * i + 7] = pack_h2(v3.z, v3.w);
}

// ---------------------------------------------------------------------------
// fp16 1-term flash attention, causal, log2-domain softmax via ex2.f16x2.
// Smem: Q 16KB + 3 x (K 8KB + V 8KB) = 64KB. 2 CTAs/SM.
// ---------------------------------------------------------------------------
#define FA_SMEM (16384 + 3 * 16384)   // 64KB

__global__ __launch_bounds__(256, 2) void flash_f16_k(
    const __half* __restrict__ qkv, __half* __restrict__ out)
{
    extern __shared__ char dsm[];
    const uint32_t sb = smem_u32(dsm);
    const uint32_t Qt = sb;

    const int tid = threadIdx.x;
    const int lid = tid & 31;
    const int w   = tid >> 5;
    const int q0  = (gridDim.x - 1 - blockIdx.x) * 128;
    const int b   = blockIdx.y >> 4;
    const int h   = blockIdx.y & 15;
    const size_t grow = (size_t)(b * SS);

    auto load_q = [&]() {
        const int row = tid >> 1;
        const int cb  = (tid & 1) * 4;
        const size_t src = (grow + q0 + row) * 3072 + h * HD;
#pragma unroll
        for (int j = 0; j < 4; ++j) {
            const int ch = cb + j;
            CP16(tile_addr(Qt, row, ch), (const char*)(qkv + src + ch * 8));
        }
    };
    auto load_kv = [&](int buf, int k0) {
        const uint32_t bbase = sb + 16384u + (uint32_t)buf * 16384u;
        const int row = tid >> 2;
        const int cb  = (tid & 3) * 2;
        const size_t srcK = (grow + k0 + row) * 3072 + 1024 + h * HD;
        const size_t srcV = srcK + 1024;
#pragma unroll
        for (int j = 0; j < 2; ++j) {
            const int ch = cb + j;
            const uint32_t off = tile_addr(0, row, ch);
            CP16(bbase + off,          (const char*)(qkv + srcK + ch * 8));
            CP16(bbase + 8192u + off,  (const char*)(qkv + srcV + ch * 8));
        }
    };

    const int nblk = q0 / 64 + 2;

    load_q();
    load_kv(0, 0);
    CP_COMMIT();
    load_kv(1, 64);
    CP_COMMIT();

    const int arow = lid & 15;
    const int achd = lid >> 4;

    uint32_t qf[4][4];
    float of[8][4];
#pragma unroll
    for (int i = 0; i < 8; ++i)
#pragma unroll
        for (int j = 0; j < 4; ++j) of[i][j] = 0.f;
    float m0 = -1e30f, m1 = -1e30f, l0 = 0.f, l1 = 0.f;

    const int row_lo = lid >> 2;
    const float SC = 0.125f * 1.44269504f;

    for (int c = 0; c < nblk; ++c) {
        if (c < nblk - 1) CP_WAIT1(); else CP_WAIT0();
        __syncthreads();
        if (c + 2 < nblk) { load_kv((c + 2) % 3, (c + 2) * 64); CP_COMMIT(); }

        if (c == 0) {
#pragma unroll
            for (int ks = 0; ks < 4; ++ks)
                ldsm4(qf[ks], tile_addr(Qt, w * 16 + arow, ks * 2 + achd));
        }

        const int k0 = c * 64;
        if (k0 > q0 + w * 16 + 15) continue;

        const uint32_t kb = sb + 16384u + (uint32_t)(c % 3) * 16384u;

        float sf[8][4];
#pragma unroll
        for (int i = 0; i < 8; ++i)
#pragma unroll
            for (int j = 0; j < 4; ++j) sf[i][j] = 0.f;

#pragma unroll
        for (int ks = 0; ks < 4; ++ks) {
            uint32_t bh[8][2];
#pragma unroll
            for (int ntp = 0; ntp < 4; ++ntp) {
                uint32_t t[4];
                ldsm4(t, tile_addr(kb, ntp * 16 + arow, ks * 2 + achd));
                bh[2 * ntp][0] = t[0]; bh[2 * ntp][1] = t[2];
                bh[2 * ntp + 1][0] = t[1]; bh[2 * ntp + 1][1] = t[3];
            }
#pragma unroll
            for (int nt = 0; nt < 8; ++nt) mma16816h(sf[nt], qf[ks], bh[nt]);
        }

        const int grow0 = q0 + w * 16 + row_lo;
        const int grow1 = grow0 + 8;
        const bool need_mask = (k0 + 63 > q0 + w * 16);
#pragma unroll
        for (int nt = 0; nt < 8; ++nt) {
            const int col = k0 + nt * 8 + 2 * (lid & 3);
#pragma unroll
            for (int j = 0; j < 4; ++j) sf[nt][j] *= SC;
            if (need_mask) {
                if (col     > grow0) sf[nt][0] = -1e30f;
                if (col + 1 > grow0) sf[nt][1] = -1e30f;
                if (col     > grow1) sf[nt][2] = -1e30f;
                if (col + 1 > grow1) sf[nt][3] = -1e30f;
            }
        }

        float tm0 = -1e30f, tm1 = -1e30f;
#pragma unroll
        for (int nt = 0; nt < 8; ++nt) {
            tm0 = fmaxf(tm0, fmaxf(sf[nt][0], sf[nt][1]));
            tm1 = fmaxf(tm1, fmaxf(sf[nt][2], sf[nt][3]));
        }
        tm0 = fmaxf(tm0, __shfl_xor_sync(0xffffffffu, tm0, 1));
        tm0 = fmaxf(tm0, __shfl_xor_sync(0xffffffffu, tm0, 2));
        tm1 = fmaxf(tm1, __shfl_xor_sync(0xffffffffu, tm1, 1));
        tm1 = fmaxf(tm1, __shfl_xor_sync(0xffffffffu, tm1, 2));

        const float mn0 = fmaxf(m0, tm0), mn1 = fmaxf(m1, tm1);
        const float cr0 = exp2f(m0 - mn0), cr1 = exp2f(m1 - mn1);
        m0 = mn0; m1 = mn1;

        uint32_t pa[4][4];
        float ps0 = 0.f, ps1 = 0.f;
#pragma unroll
        for (int nt = 0; nt < 8; ++nt) {
            const uint32_t p01 = ex2_h2(sf[nt][0] - mn0, sf[nt][1] - mn0);
            const uint32_t p23 = ex2_h2(sf[nt][2] - mn1, sf[nt][3] - mn1);
            pa[nt >> 1][(nt & 1) * 2 + 0] = p01;
            pa[nt >> 1][(nt & 1) * 2 + 1] = p23;
            const float2 f01 = __half22float2(*(const __half2*)&p01);
            const float2 f23 = __half22float2(*(const __half2*)&p23);
            ps0 += f01.x + f01.y;
            ps1 += f23.x + f23.y;
        }
        ps0 += __shfl_xor_sync(0xffffffffu, ps0, 1);
        ps0 += __shfl_xor_sync(0xffffffffu, ps0, 2);
        ps1 += __shfl_xor_sync(0xffffffffu, ps1, 1);
        ps1 += __shfl_xor_sync(0xffffffffu, ps1, 2);
        l0 = l0 * cr0 + ps0;
        l1 = l1 * cr1 + ps1;
#pragma unroll
        for (int nt = 0; nt < 8; ++nt) {
            of[nt][0] *= cr0; of[nt][1] *= cr0;
            of[nt][2] *= cr1; of[nt][3] *= cr1;
        }

        const uint32_t vb = kb + 8192u;
#pragma unroll
        for (int ks = 0; ks < 4; ++ks) {
            uint32_t vh[8][2];
#pragma unroll
            for (int ntp = 0; ntp < 4; ++ntp) {
                const int krow = ks * 16 + arow;
                uint32_t t[4];
                ldsm4t(t, tile_addr(vb, krow, ntp * 2 + achd));
                vh[2 * ntp][0] = t[0]; vh[2 * ntp][1] = t[1];
                vh[2 * ntp + 1][0] = t[2]; vh[2 * ntp + 1][1] = t[3];
            }
#pragma unroll
            for (int nt = 0; nt < 8; ++nt) mma16816h(of[nt], pa[ks], vh[nt]);
        }
    }

    const float iv0 = 1.0f / l0, iv1 = 1.0f / l1;
    const size_t r0 = (grow + q0 + w * 16 + row_lo) * DD + h * HD;
    const size_t r1 = r0 + 8 * DD;
#pragma unroll
    for (int nt = 0; nt < 8; ++nt) {
        const int cofs = nt * 8 + 2 * (lid & 3);
        *(uint32_t*)(out + r0 + cofs) = pack_h2(of[nt][0] * iv0, of[nt][1] * iv0);
        *(uint32_t*)(out + r1 + cofs) = pack_h2(of[nt][2] * iv1, of[nt][3] * iv1);
    }
}

// ---------------------------------------------------------------------------
// LayerNorm with fused split-K reduction: in = p0 + p1 + colbias + res.
// One block (256 thr) per row of 1024; optional fp32 + fp16 outputs.
// ---------------------------------------------------------------------------
__global__ __launch_bounds__(256) void layernorm2_k(
    const float* __restrict__ p0, const float* __restrict__ p1,
    const float* __restrict__ res, const float* __restrict__ cb,
    const float* __restrict__ w, const float* __restrict__ b,
    float* __restrict__ out, __half* __restrict__ of16)
{
    __shared__ float red[8];
    __shared__ float bval;
    const int tid = threadIdx.x;
    const size_t base = (size_t)blockIdx.x * DD;

    float4 v  = ((const float4*)(p0 + base))[tid];
    float4 v1 = ((const float4*)(p1 + base))[tid];
    float4 vr = ((const float4*)(res + base))[tid];
    float4 vb = ((const float4*)cb)[tid];
    v.x += v1.x + vr.x + vb.x;
    v.y += v1.y + vr.y + vb.y;
    v.z += v1.z + vr.z + vb.z;
    v.w += v1.w + vr.w + vb.w;

    float s = v.x + v.y + v.z + v.w;
#pragma unroll
    for (int off = 16; off; off >>= 1) s += __shfl_xor_sync(0xffffffffu, s, off);
    if ((tid & 31) == 0) red[tid >> 5] = s;
    __syncthreads();
    if (tid == 0) {
        float t = 0.f;
#pragma unroll
        for (int i = 0; i < 8; ++i) t += red[i];
        bval = t * (1.0f / DD);
    }
    __syncthreads();
    const float mu = bval;
    __syncthreads();

    float dx = v.x - mu, dy = v.y - mu, dz = v.z - mu, dw = v.w - mu;
    float q = dx * dx + dy * dy + dz * dz + dw * dw;
#pragma unroll
    for (int off = 16; off; off >>= 1) q += __shfl_xor_sync(0xffffffffu, q, off);
    if ((tid & 31) == 0) red[tid >> 5] = q;
    __syncthreads();
    if (tid == 0) {
        float t = 0.f;
#pragma unroll
        for (int i = 0; i < 8; ++i) t += red[i];
        bval = t * (1.0f / DD);
    }
    __syncthreads();
    const float inv = rsqrtf(bval + 1e-5f);

    float4 w4 = ((const float4*)w)[tid];
    float4 b4 = ((const float4*)b)[tid];
    float4 r = make_float4(dx * inv * w4.x + b4.x,
                           dy * inv * w4.y + b4.y,
                           dz * inv * w4.z + b4.z,
                           dw * inv * w4.w + b4.w);
    if (out) ((float4*)(out + base))[tid] = r;
    if (of16) {
        *(uint32_t*)(of16 + base + 4 * tid)     = pack_h2(r.x, r.y);
        *(uint32_t*)(of16 + base + 4 * tid + 2) = pack_h2(r.z, r.w);
    }
}

// ---------------------------------------------------------------------------
// Launch
// ---------------------------------------------------------------------------
extern "C" void kernel_launch(void* const* d_in, const int* in_sizes, int n_in,
                              void* d_out, int out_size)
{
    const float* x     = (const float*)d_in[0];
    const float* qkv_w = (const float*)d_in[1];
    const float* qkv_b = (const float*)d_in[2];
    const float* out_w = (const float*)d_in[3];
    const float* out_b = (const float*)d_in[4];
    const float* w1    = (const float*)d_in[5];
    const float* b1    = (const float*)d_in[6];
    const float* w2    = (const float*)d_in[7];
    const float* b2    = (const float*)d_in[8];
    const float* ln1w  = (const float*)d_in[9];
    const float* ln1b  = (const float*)d_in[10];
    const float* ln2w  = (const float*)d_in[11];
    const float* ln2b  = (const float*)d_in[12];

    float* outp = (float*)d_out;
    float* kdst = outp + (size_t)MTOK * DD;
    float* vdst = outp + (size_t)2 * MTOK * DD;

    float *part, *h1;
    __half *qkvf, *af, *h1f, *midf, *xf, *wqf, *owf, *w1f, *w2f;
    cudaGetSymbolAddress((void**)&qkvf,  g_qkvf);
    cudaGetSymbolAddress((void**)&af,    g_af);
    cudaGetSymbolAddress((void**)&part,  g_part);
    cudaGetSymbolAddress((void**)&h1,    g_h1);
    cudaGetSymbolAddress((void**)&h1f,   g_h1f);
    cudaGetSymbolAddress((void**)&midf,  g_midf);
    cudaGetSymbolAddress((void**)&xf,    g_xf);
    cudaGetSymbolAddress((void**)&wqf,   g_wqf);
    cudaGetSymbolAddress((void**)&owf,   g_owf);
    cudaGetSymbolAddress((void**)&w1f,   g_w1f);
    cudaGetSymbolAddress((void**)&w2f,   g_w2f);

    cudaFuncSetAttribute(gemm_f16_1t,
                         cudaFuncAttributeMaxDynamicSharedMemorySize, GEMM1_SMEM);
    cudaFuncSetAttribute(flash_f16_k,
                         cudaFuncAttributeMaxDynamicSharedMemorySize, FA_SMEM);

    // 0) all fp32->fp16 conversions in ONE launch
    cvt_all_k<<<CVT_BLOCKS, 256>>>(
        (const float4*)qkv_w, (const float4*)out_w, (const float4*)w1,
        (const float4*)w2, (const float4*)x,
        (uint32_t*)wqf, (uint32_t*)owf, (uint32_t*)w1f,
        (uint32_t*)w2f, (uint32_t*)xf);

    // 1) QKV projection -> qkv fp16 single; k/v fp32 to d_out
    gemm_f16_1t<<<dim3(3072 / 128, MTOK / 128, 1), 256, GEMM1_SMEM>>>(
        xf, wqf, qkv_b, nullptr, nullptr, qkvf, kdst, vdst,
        MTOK, 3 * DD, DD, 0);
    // 2) flash attention -> attn fp16 single
    flash_f16_k<<<dim3(SS / 128, BB * HH), 256, FA_SMEM>>>(qkvf, af);
    // 3) out projection, split-K=2 -> fp32 partials
    gemm_f16_1t<<<dim3(DD / 128, MTOK / 128, 2), 256, GEMM1_SMEM>>>(
        af, owf, nullptr, nullptr, part, nullptr, nullptr, nullptr,
        MTOK, DD, DD, 0);
    // 4) LN1 with fused reduction: p0+p1+out_b+x -> h1 fp32 + h1f fp16
    layernorm2_k<<<MTOK, 256>>>(part, part + (size_t)MTOK * DD, x, out_b,
                                ln1w, ln1b, h1, h1f);
    // 5) MLP up + ReLU -> midf fp16
    gemm_f16_1t<<<dim3(FF_DIM / 128, MTOK / 128, 1), 256, GEMM1_SMEM>>>(
        h1f, w1f, b1, nullptr, nullptr, midf, nullptr, nullptr,
        MTOK, FF_DIM, DD, 1);
    // 6) MLP down, split-K=2 -> fp32 partials
    gemm_f16_1t<<<dim3(DD / 128, MTOK / 128, 2), 256, GEMM1_SMEM>>>(
        midf, w2f, nullptr, nullptr, part, nullptr, nullptr, nullptr,
        MTOK, DD, FF_DIM, 0);
    // 7) LN2 with fused reduction: p0+p1+b2+h1 -> out
    layernorm2_k<<<MTOK, 256>>>(part, part + (size_t)MTOK * DD, h1, b2,
                                ln2w, ln2b, outp, nullptr);
}

// round 16
// speedup vs baseline: 1.0409x; 1.0129x over previous
#include <cuda_runtime.h>
#include <cuda_fp16.h>
#include <cstdint>

// Problem constants: B=2, S=2048, D=1024, H=16, hd=64, FF=4096
#define BB 2
#define SS 2048
#define DD 1024
#define HH 16
#define HD 64
#define FF_DIM 4096
#define MTOK (BB*SS)          // 4096 rows

// ---------------------------------------------------------------------------
// Scratch (device globals; no allocation allowed)
// ---------------------------------------------------------------------------
__device__ __half g_qkvf[(size_t)MTOK * 3 * DD];
__device__ __half g_af[(size_t)MTOK * DD];
__device__ float  g_part[(size_t)4 * MTOK * DD];   // split-K partials (reused)
__device__ float  g_h1[(size_t)MTOK * DD];
__device__ __half g_h1f[(size_t)MTOK * DD];
__device__ __half g_midf[(size_t)MTOK * FF_DIM];
__device__ __half g_xf[(size_t)MTOK * DD];
__device__ __half g_wqf[(size_t)3 * DD * DD];
__device__ __half g_owf[(size_t)DD * DD];
__device__ __half g_w1f[(size_t)FF_DIM * DD];
__device__ __half g_w2f[(size_t)DD * FF_DIM];

// ---------------------------------------------------------------------------
// MMA / ldmatrix / cp.async helpers
// ---------------------------------------------------------------------------
__device__ __forceinline__ uint32_t smem_u32(const void* p) {
    uint32_t a;
    asm("{ .reg .u64 t; cvta.to.shared.u64 t, %1; cvt.u32.u64 %0, t; }"
        : "=r"(a) : "l"(p));
    return a;
}
__device__ __forceinline__ void ldsm4(uint32_t* r, uint32_t a) {
    asm volatile("ldmatrix.sync.aligned.m8n8.x4.shared.b16 {%0,%1,%2,%3}, [%4];"
                 : "=r"(r[0]), "=r"(r[1]), "=r"(r[2]), "=r"(r[3]) : "r"(a));
}
__device__ __forceinline__ void ldsm4t(uint32_t* r, uint32_t a) {
    asm volatile("ldmatrix.sync.aligned.m8n8.x4.trans.shared.b16 {%0,%1,%2,%3}, [%4];"
                 : "=r"(r[0]), "=r"(r[1]), "=r"(r[2]), "=r"(r[3]) : "r"(a));
}
__device__ __forceinline__ void mma16816h(float* c, const uint32_t* a, const uint32_t* b) {
    asm volatile(
        "mma.sync.aligned.m16n8k16.row.col.f32.f16.f16.f32 "
        "{%0,%1,%2,%3}, {%4,%5,%6,%7}, {%8,%9}, {%0,%1,%2,%3};"
        : "+f"(c[0]), "+f"(c[1]), "+f"(c[2]), "+f"(c[3])
        : "r"(a[0]), "r"(a[1]), "r"(a[2]), "r"(a[3]), "r"(b[0]), "r"(b[1]));
}
#define CP16(dst, src) \
    asm volatile("cp.async.cg.shared.global [%0], [%1], 16;" :: "r"(dst), "l"(src) : "memory")
#define CP_COMMIT() asm volatile("cp.async.commit_group;" ::: "memory")
#define CP_WAIT1()  asm volatile("cp.async.wait_group 1;" ::: "memory")
#define CP_WAIT0()  asm volatile("cp.async.wait_group 0;" ::: "memory")

// 128B-row tile: row stride 128B (8 x 16B chunks), chunk swizzled by row&7.
__device__ __forceinline__ uint32_t tile_addr(uint32_t base, int row, int ch) {
    return base + (uint32_t)row * 128u + (uint32_t)((ch ^ (row & 7)) << 4);
}
__device__ __forceinline__ uint32_t pack_h2(float a, float b) {
    __half2 h = __halves2half2(__float2half(a), __float2half(b));
    return *(uint32_t*)&h;
}
__device__ __forceinline__ uint32_t ex2_h2(float a, float b) {
    uint32_t packed = pack_h2(a, b);
    uint32_t r;
    asm("ex2.approx.f16x2 %0, %1;" : "=r"(r) : "r"(packed));
    return r;
}

// ---------------------------------------------------------------------------
// fp16 1-term GEMM. Supports split-K via blockIdx.z: each z-slice computes
// K/gridDim.z and writes its fp32 partial to C + z*M*N (bias nullable).
// K-stage 64: 3 stages x 32KB = 96KB smem; 2 CTAs/SM.
// ---------------------------------------------------------------------------
#define GEMM1_SMEM (3 * 32768)   // 96KB

__global__ __launch_bounds__(256, 2) void gemm_f16_1t(
    const __half* __restrict__ A, const __half* __restrict__ W,
    const float* __restrict__ bias, const float* __restrict__ res,
    float* __restrict__ C, __half* __restrict__ Cf,
    float* __restrict__ kd, float* __restrict__ vd,
    int M, int N, int K, int relu)
{
    extern __shared__ char dsm[];
    const uint32_t sb = smem_u32(dsm);

    const int tid = threadIdx.x;
    const int lid = tid & 31;
    const int wid = tid >> 5;
    const int wm = wid & 1;
    const int wn = wid >> 1;
    const int bm = blockIdx.y * 128, bn = blockIdx.x * 128;
    const int kz = blockIdx.z;
    const int Ks = K / gridDim.z;

    const __half* gA = A + (size_t)bm * K + (size_t)kz * Ks;
    const __half* gW = W + (size_t)bn * K + (size_t)kz * Ks;
    float* Cz = C ? C + (size_t)kz * M * N : nullptr;

    float acc[4][4][4];
#pragma unroll
    for (int i = 0; i < 4; ++i)
#pragma unroll
        for (int j = 0; j < 4; ++j)
#pragma unroll
            for (int k = 0; k < 4; ++k) acc[i][j][k] = 0.f;

    const int NC = Ks >> 6;           // K-chunks of 64

    auto load_stage = [&](int stage, int kk) {
        const uint32_t stb = sb + (uint32_t)stage * 32768u;
        const int r  = tid >> 1;
        const int c0 = (tid & 1) * 4;
        const __half* ga = gA + kk + (size_t)r * K;
        const __half* gw = gW + kk + (size_t)r * K;
#pragma unroll
        for (int j = 0; j < 4; ++j) {
            const int ch = c0 + j;
            CP16(tile_addr(stb, r, ch),            (const char*)(ga + ch * 8));
            CP16(tile_addr(stb + 16384u, r, ch),   (const char*)(gw + ch * 8));
        }
        CP_COMMIT();
    };

    load_stage(0, 0);
    if (NC > 1) load_stage(1, 64); else CP_COMMIT();

    const int arow = lid & 15;
    const int achd = lid >> 4;

    for (int c = 0; c < NC; ++c) {
        if (c < NC - 1) CP_WAIT1(); else CP_WAIT0();
        __syncthreads();
        if (c + 2 < NC) load_stage((c + 2) % 3, (c + 2) << 6);

        const uint32_t stb = sb + (uint32_t)(c % 3) * 32768u;

#pragma unroll
        for (int ks = 0; ks < 4; ++ks) {
            const int chk = ks * 2 + achd;
            uint32_t af[4][4];
#pragma unroll
            for (int mt = 0; mt < 4; ++mt) {
                const int r = wm * 64 + mt * 16 + arow;
                ldsm4(af[mt], tile_addr(stb, r, chk));
            }
            uint32_t bf[4][2];
#pragma unroll
            for (int ntp = 0; ntp < 2; ++ntp) {
                const int r = wn * 32 + ntp * 16 + arow;
                uint32_t t[4];
                ldsm4(t, tile_addr(stb + 16384u, r, chk));
                bf[2 * ntp][0] = t[0]; bf[2 * ntp][1] = t[2];
                bf[2 * ntp + 1][0] = t[1]; bf[2 * ntp + 1][1] = t[3];
            }
#pragma unroll
            for (int mt = 0; mt < 4; ++mt)
#pragma unroll
                for (int nt = 0; nt < 4; ++nt)
                    mma16816h(acc[mt][nt], af[mt], bf[nt]);
        }
    }

    const int l4 = lid >> 2;
    const int l2 = (lid & 3) * 2;
#pragma unroll
    for (int mt = 0; mt < 4; ++mt) {
#pragma unroll
        for (int nt = 0; nt < 4; ++nt) {
            const int col = bn + wn * 32 + nt * 8 + l2;
#pragma unroll
            for (int half = 0; half < 2; ++half) {
                const int row = bm + wm * 64 + mt * 16 + l4 + half * 8;
                float v0 = acc[mt][nt][2 * half + 0];
                float v1 = acc[mt][nt][2 * half + 1];
                if (bias) { v0 += bias[col]; v1 += bias[col + 1]; }
                const size_t o = (size_t)row * N + col;
                if (res) { v0 += res[o]; v1 += res[o + 1]; }
                if (relu) { v0 = fmaxf(v0, 0.f); v1 = fmaxf(v1, 0.f); }
                if (Cz) *(float2*)(Cz + o) = make_float2(v0, v1);
                if (kd) {
                    if (col >= 2048)
                        *(float2*)(vd + (size_t)row * DD + col - 2048) = make_float2(v0, v1);
                    else if (col >= 1024)
                        *(float2*)(kd + (size_t)row * DD + col - 1024) = make_float2(v0, v1);
                }
                if (Cf) *(uint32_t*)(Cf + o) = pack_h2(v0, v1);
            }
        }
    }
}

// ---------------------------------------------------------------------------
// Fused fp32->fp16 conversion of all 5 arrays in ONE launch.
// ---------------------------------------------------------------------------
#define CVT_TOTAL4 4194304
#define CVT_BLOCKS ((CVT_TOTAL4 / 4) / 256)

__global__ __launch_bounds__(256) void cvt_all_k(
    const float4* __restrict__ s0, const float4* __restrict__ s1,
    const float4* __restrict__ s2, const float4* __restrict__ s3,
    const float4* __restrict__ s4,
    uint32_t* __restrict__ d0, uint32_t* __restrict__ d1,
    uint32_t* __restrict__ d2, uint32_t* __restrict__ d3,
    uint32_t* __restrict__ d4)
{
    const size_t g = (size_t)(blockIdx.x * blockDim.x + threadIdx.x) * 4;
    const float4* s;
    uint32_t* d;
    size_t off;
    if (g < 786432u)       { s = s0; d = d0; off = 0; }
    else if (g < 1048576u) { s = s1; d = d1; off = 786432u; }
    else if (g < 2097152u) { s = s2; d = d2; off = 1048576u; }
    else if (g < 3145728u) { s = s3; d = d3; off = 2097152u; }
    else                   { s = s4; d = d4; off = 3145728u; }
    const size_t i = g - off;
    float4 v0 = s[i], v1 = s[i + 1], v2 = s[i + 2], v3 = s[i + 3];
    d[2 * i + 0] = pack_h2(v0.x, v0.y);
    d[2 * i + 1] = pack_h2(v0.z, v0.w);
    d[2 * i + 2] = pack_h2(v1.x, v1.y);
    d[2 * i + 3] = pack_h2(v1.z, v1.w);
    d[2 * i + 4] = pack_h2(v2.x, v2.y);
    d[2 * i + 5] = pack_h2(v2.z, v2.w);
    d[2 * i + 6] = pack_h2(v3.x, v3.y);
    d[2 * i + 7] = pack_h2(v3.z, v3.w);
}

// ---------------------------------------------------------------------------
// fp16 1-term flash attention, causal, log2-domain softmax via ex2.f16x2.
// Smem: Q 16KB + 3 x (K 8KB + V 8KB) = 64KB. 2 CTAs/SM.
// ---------------------------------------------------------------------------
#define FA_SMEM (16384 + 3 * 16384)   // 64KB

__global__ __launch_bounds__(256, 2) void flash_f16_k(
    const __half* __restrict__ qkv, __half* __restrict__ out)
{
    extern __shared__ char dsm[];
    const uint32_t sb = smem_u32(dsm);
    const uint32_t Qt = sb;

    const int tid = threadIdx.x;
    const int lid = tid & 31;
    const int w   = tid >> 5;
    const int q0  = (gridDim.x - 1 - blockIdx.x) * 128;
    const int b   = blockIdx.y >> 4;
    const int h   = blockIdx.y & 15;
    const size_t grow = (size_t)(b * SS);

    auto load_q = [&]() {
        const int row = tid >> 1;
        const int cb  = (tid & 1) * 4;
        const size_t src = (grow + q0 + row) * 3072 + h * HD;
#pragma unroll
        for (int j = 0; j < 4; ++j) {
            const int ch = cb + j;
            CP16(tile_addr(Qt, row, ch), (const char*)(qkv + src + ch * 8));
        }
    };
    auto load_kv = [&](int buf, int k0) {
        const uint32_t bbase = sb + 16384u + (uint32_t)buf * 16384u;
        const int row = tid >> 2;
        const int cb  = (tid & 3) * 2;
        const size_t srcK = (grow + k0 + row) * 3072 + 1024 + h * HD;
        const size_t srcV = srcK + 1024;
#pragma unroll
        for (int j = 0; j < 2; ++j) {
            const int ch = cb + j;
            const uint32_t off = tile_addr(0, row, ch);
            CP16(bbase + off,          (const char*)(qkv + srcK + ch * 8));
            CP16(bbase + 8192u + off,  (const char*)(qkv + srcV + ch * 8));
        }
    };

    const int nblk = q0 / 64 + 2;

    load_q();
    load_kv(0, 0);
    CP_COMMIT();
    load_kv(1, 64);
    CP_COMMIT();

    const int arow = lid & 15;
    const int achd = lid >> 4;

    uint32_t qf[4][4];
    float of[8][4];
#pragma unroll
    for (int i = 0; i < 8; ++i)
#pragma unroll
        for (int j = 0; j < 4; ++j) of[i][j] = 0.f;
    float m0 = -1e30f, m1 = -1e30f, l0 = 0.f, l1 = 0.f;

    const int row_lo = lid >> 2;
    const float SC = 0.125f * 1.44269504f;

    for (int c = 0; c < nblk; ++c) {
        if (c < nblk - 1) CP_WAIT1(); else CP_WAIT0();
        __syncthreads();
        if (c + 2 < nblk) { load_kv((c + 2) % 3, (c + 2) * 64); CP_COMMIT(); }

        if (c == 0) {
#pragma unroll
            for (int ks = 0; ks < 4; ++ks)
                ldsm4(qf[ks], tile_addr(Qt, w * 16 + arow, ks * 2 + achd));
        }

        const int k0 = c * 64;
        if (k0 > q0 + w * 16 + 15) continue;

        const uint32_t kb = sb + 16384u + (uint32_t)(c % 3) * 16384u;

        float sf[8][4];
#pragma unroll
        for (int i = 0; i < 8; ++i)
#pragma unroll
            for (int j = 0; j < 4; ++j) sf[i][j] = 0.f;

#pragma unroll
        for (int ks = 0; ks < 4; ++ks) {
            uint32_t bh[8][2];
#pragma unroll
            for (int ntp = 0; ntp < 4; ++ntp) {
                uint32_t t[4];
                ldsm4(t, tile_addr(kb, ntp * 16 + arow, ks * 2 + achd));
                bh[2 * ntp][0] = t[0]; bh[2 * ntp][1] = t[2];
                bh[2 * ntp + 1][0] = t[1]; bh[2 * ntp + 1][1] = t[3];
            }
#pragma unroll
            for (int nt = 0; nt < 8; ++nt) mma16816h(sf[nt], qf[ks], bh[nt]);
        }

        const int grow0 = q0 + w * 16 + row_lo;
        const int grow1 = grow0 + 8;
        const bool need_mask = (k0 + 63 > q0 + w * 16);
#pragma unroll
        for (int nt = 0; nt < 8; ++nt) {
            const int col = k0 + nt * 8 + 2 * (lid & 3);
#pragma unroll
            for (int j = 0; j < 4; ++j) sf[nt][j] *= SC;
            if (need_mask) {
                if (col     > grow0) sf[nt][0] = -1e30f;
                if (col + 1 > grow0) sf[nt][1] = -1e30f;
                if (col     > grow1) sf[nt][2] = -1e30f;
                if (col + 1 > grow1) sf[nt][3] = -1e30f;
            }
        }

        float tm0 = -1e30f, tm1 = -1e30f;
#pragma unroll
        for (int nt = 0; nt < 8; ++nt) {
            tm0 = fmaxf(tm0, fmaxf(sf[nt][0], sf[nt][1]));
            tm1 = fmaxf(tm1, fmaxf(sf[nt][2], sf[nt][3]));
        }
        tm0 = fmaxf(tm0, __shfl_xor_sync(0xffffffffu, tm0, 1));
        tm0 = fmaxf(tm0, __shfl_xor_sync(0xffffffffu, tm0, 2));
        tm1 = fmaxf(tm1, __shfl_xor_sync(0xffffffffu, tm1, 1));
        tm1 = fmaxf(tm1, __shfl_xor_sync(0xffffffffu, tm1, 2));

        const float mn0 = fmaxf(m0, tm0), mn1 = fmaxf(m1, tm1);
        const float cr0 = exp2f(m0 - mn0), cr1 = exp2f(m1 - mn1);
        m0 = mn0; m1 = mn1;

        uint32_t pa[4][4];
        float ps0 = 0.f, ps1 = 0.f;
#pragma unroll
        for (int nt = 0; nt < 8; ++nt) {
            const uint32_t p01 = ex2_h2(sf[nt][0] - mn0, sf[nt][1] - mn0);
            const uint32_t p23 = ex2_h2(sf[nt][2] - mn1, sf[nt][3] - mn1);
            pa[nt >> 1][(nt & 1) * 2 + 0] = p01;
            pa[nt >> 1][(nt & 1) * 2 + 1] = p23;
            const float2 f01 = __half22float2(*(const __half2*)&p01);
            const float2 f23 = __half22float2(*(const __half2*)&p23);
            ps0 += f01.x + f01.y;
            ps1 += f23.x + f23.y;
        }
        ps0 += __shfl_xor_sync(0xffffffffu, ps0, 1);
        ps0 += __shfl_xor_sync(0xffffffffu, ps0, 2);
        ps1 += __shfl_xor_sync(0xffffffffu, ps1, 1);
        ps1 += __shfl_xor_sync(0xffffffffu, ps1, 2);
        l0 = l0 * cr0 + ps0;
        l1 = l1 * cr1 + ps1;
#pragma unroll
        for (int nt = 0; nt < 8; ++nt) {
            of[nt][0] *= cr0; of[nt][1] *= cr0;
            of[nt][2] *= cr1; of[nt][3] *= cr1;
        }

        const uint32_t vb = kb + 8192u;
#pragma unroll
        for (int ks = 0; ks < 4; ++ks) {
            uint32_t vh[8][2];
#pragma unroll
            for (int ntp = 0; ntp < 4; ++ntp) {
                const int krow = ks * 16 + arow;
                uint32_t t[4];
                ldsm4t(t, tile_addr(vb, krow, ntp * 2 + achd));
                vh[2 * ntp][0] = t[0]; vh[2 * ntp][1] = t[1];
                vh[2 * ntp + 1][0] = t[2]; vh[2 * ntp + 1][1] = t[3];
            }
#pragma unroll
            for (int nt = 0; nt < 8; ++nt) mma16816h(of[nt], pa[ks], vh[nt]);
        }
    }

    const float iv0 = 1.0f / l0, iv1 = 1.0f / l1;
    const size_t r0 = (grow + q0 + w * 16 + row_lo) * DD + h * HD;
    const size_t r1 = r0 + 8 * DD;
#pragma unroll
    for (int nt = 0; nt < 8; ++nt) {
        const int cofs = nt * 8 + 2 * (lid & 3);
        *(uint32_t*)(out + r0 + cofs) = pack_h2(of[nt][0] * iv0, of[nt][1] * iv0);
        *(uint32_t*)(out + r1 + cofs) = pack_h2(of[nt][2] * iv1, of[nt][3] * iv1);
    }
}

// ---------------------------------------------------------------------------
// LayerNorm with fused split-K reduction: in = sum_{p<np} part[p] + cb + res.
// One block (256 thr) per row of 1024; optional fp32 + fp16 outputs.
// ---------------------------------------------------------------------------
__global__ __launch_bounds__(256) void layernormN_k(
    const float* __restrict__ parts, int np,
    const float* __restrict__ res, const float* __restrict__ cb,
    const float* __restrict__ w, const float* __restrict__ b,
    float* __restrict__ out, __half* __restrict__ of16)
{
    __shared__ float red[8];
    __shared__ float bval;
    const int tid = threadIdx.x;
    const size_t base = (size_t)blockIdx.x * DD;
    const size_t stride = (size_t)MTOK * DD;

    float4 v  = ((const float4*)(parts + base))[tid];
    for (int p = 1; p < np; ++p) {
        float4 vp = ((const float4*)(parts + p * stride + base))[tid];
        v.x += vp.x; v.y += vp.y; v.z += vp.z; v.w += vp.w;
    }
    float4 vr = ((const float4*)(res + base))[tid];
    float4 vb = ((const float4*)cb)[tid];
    v.x += vr.x + vb.x;
    v.y += vr.y + vb.y;
    v.z += vr.z + vb.z;
    v.w += vr.w + vb.w;

    float s = v.x + v.y + v.z + v.w;
#pragma unroll
    for (int off = 16; off; off >>= 1) s += __shfl_xor_sync(0xffffffffu, s, off);
    if ((tid & 31) == 0) red[tid >> 5] = s;
    __syncthreads();
    if (tid == 0) {
        float t = 0.f;
#pragma unroll
        for (int i = 0; i < 8; ++i) t += red[i];
        bval = t * (1.0f / DD);
    }
    __syncthreads();
    const float mu = bval;
    __syncthreads();

    float dx = v.x - mu, dy = v.y - mu, dz = v.z - mu, dw = v.w - mu;
    float q = dx * dx + dy * dy + dz * dz + dw * dw;
#pragma unroll
    for (int off = 16; off; off >>= 1) q += __shfl_xor_sync(0xffffffffu, q, off);
    if ((tid & 31) == 0) red[tid >> 5] = q;
    __syncthreads();
    if (tid == 0) {
        float t = 0.f;
#pragma unroll
        for (int i = 0; i < 8; ++i) t += red[i];
        bval = t * (1.0f / DD);
    }
    __syncthreads();
    const float inv = rsqrtf(bval + 1e-5f);

    float4 w4 = ((const float4*)w)[tid];
    float4 b4 = ((const float4*)b)[tid];
    float4 r = make_float4(dx * inv * w4.x + b4.x,
                           dy * inv * w4.y + b4.y,
                           dz * inv * w4.z + b4.z,
                           dw * inv * w4.w + b4.w);
    if (out) ((float4*)(out + base))[tid] = r;
    if (of16) {
        *(uint32_t*)(of16 + base + 4 * tid)     = pack_h2(r.x, r.y);
        *(uint32_t*)(of16 + base + 4 * tid + 2) = pack_h2(r.z, r.w);
    }
}

// ---------------------------------------------------------------------------
// Launch
// ---------------------------------------------------------------------------
extern "C" void kernel_launch(void* const* d_in, const int* in_sizes, int n_in,
                              void* d_out, int out_size)
{
    const float* x     = (const float*)d_in[0];
    const float* qkv_w = (const float*)d_in[1];
    const float* qkv_b = (const float*)d_in[2];
    const float* out_w = (const float*)d_in[3];
    const float* out_b = (const float*)d_in[4];
    const float* w1    = (const float*)d_in[5];
    const float* b1    = (const float*)d_in[6];
    const float* w2    = (const float*)d_in[7];
    const float* b2    = (const float*)d_in[8];
    const float* ln1w  = (const float*)d_in[9];
    const float* ln1b  = (const float*)d_in[10];
    const float* ln2w  = (const float*)d_in[11];
    const float* ln2b  = (const float*)d_in[12];

    float* outp = (float*)d_out;
    float* kdst = outp + (size_t)MTOK * DD;
    float* vdst = outp + (size_t)2 * MTOK * DD;

    float *part, *h1;
    __half *qkvf, *af, *h1f, *midf, *xf, *wqf, *owf, *w1f, *w2f;
    cudaGetSymbolAddress((void**)&qkvf,  g_qkvf);
    cudaGetSymbolAddress((void**)&af,    g_af);
    cudaGetSymbolAddress((void**)&part,  g_part);
    cudaGetSymbolAddress((void**)&h1,    g_h1);
    cudaGetSymbolAddress((void**)&h1f,   g_h1f);
    cudaGetSymbolAddress((void**)&midf,  g_midf);
    cudaGetSymbolAddress((void**)&xf,    g_xf);
    cudaGetSymbolAddress((void**)&wqf,   g_wqf);
    cudaGetSymbolAddress((void**)&owf,   g_owf);
    cudaGetSymbolAddress((void**)&w1f,   g_w1f);
    cudaGetSymbolAddress((void**)&w2f,   g_w2f);

    cudaFuncSetAttribute(gemm_f16_1t,
                         cudaFuncAttributeMaxDynamicSharedMemorySize, GEMM1_SMEM);
    cudaFuncSetAttribute(flash_f16_k,
                         cudaFuncAttributeMaxDynamicSharedMemorySize, FA_SMEM);

    // 0) all fp32->fp16 conversions in ONE launch
    cvt_all_k<<<CVT_BLOCKS, 256>>>(
        (const float4*)qkv_w, (const float4*)out_w, (const float4*)w1,
        (const float4*)w2, (const float4*)x,
        (uint32_t*)wqf, (uint32_t*)owf, (uint32_t*)w1f,
        (uint32_t*)w2f, (uint32_t*)xf);

    // 1) QKV projection -> qkv fp16 single; k/v fp32 to d_out
    gemm_f16_1t<<<dim3(3072 / 128, MTOK / 128, 1), 256, GEMM1_SMEM>>>(
        xf, wqf, qkv_b, nullptr, nullptr, qkvf, kdst, vdst,
        MTOK, 3 * DD, DD, 0);
    // 2) flash attention -> attn fp16 single
    flash_f16_k<<<dim3(SS / 128, BB * HH), 256, FA_SMEM>>>(qkvf, af);
    // 3) out projection, split-K=2 -> fp32 partials
    gemm_f16_1t<<<dim3(DD / 128, MTOK / 128, 2), 256, GEMM1_SMEM>>>(
        af, owf, nullptr, nullptr, part, nullptr, nullptr, nullptr,
        MTOK, DD, DD, 0);
    // 4) LN1 with fused reduction: p0+p1+out_b+x -> h1 fp32 + h1f fp16
    layernormN_k<<<MTOK, 256>>>(part, 2, x, out_b, ln1w, ln1b, h1, h1f);
    // 5) MLP up + ReLU -> midf fp16
    gemm_f16_1t<<<dim3(FF_DIM / 128, MTOK / 128, 1), 256, GEMM1_SMEM>>>(
        h1f, w1f, b1, nullptr, nullptr, midf, nullptr, nullptr,
        MTOK, FF_DIM, DD, 1);
    // 6) MLP down, split-K=4 -> fp32 partials
    gemm_f16_1t<<<dim3(DD / 128, MTOK / 128, 4), 256, GEMM1_SMEM>>>(
        midf, w2f, nullptr, nullptr, part, nullptr, nullptr, nullptr,
        MTOK, DD, FF_DIM, 0);
    // 7) LN2 with fused reduction: p0..p3+b2+h1 -> out
    layernormN_k<<<MTOK, 256>>>(part, 4, h1, b2, ln2w, ln2b, outp, nullptr);
}